// round 14
// baseline (speedup 1.0000x reference)
#include <cuda_runtime.h>
#include <math.h>

// ---------------- problem constants ----------------
#define BQ   8
#define LQ   128
#define TSEQ 384          // 3 * L tokens per batch
#define MTOK 3072         // BQ * TSEQ
#define DM   256          // d_model
#define DI   512          // d_inner
#define DS   16           // d_state
#define RK   16           // dt_rank
#define NL   4

// ---------------- scratch (device globals; no allocation allowed) ----------------
__device__ float g_u  [MTOK * DM];
__device__ float g_res[MTOK * DM];
__device__ float g_rs [MTOK];          // per-row rmsnorm scales
__device__ float g_xz [MTOK * 2 * DI];
__device__ float g_xc [MTOK * DI];
__device__ float g_proj[MTOK * 48];
__device__ float g_y  [MTOK * DI];

// ---------------- embeddings + interleave -> u ----------------
__global__ void k_embed(const float* __restrict__ states,
                        const float* __restrict__ actions,
                        const float* __restrict__ goal,
                        const int*   __restrict__ timesteps,
                        const float* __restrict__ te_W,
                        const float* __restrict__ se_W, const float* __restrict__ se_b,
                        const float* __restrict__ ge_W, const float* __restrict__ ge_b,
                        const float* __restrict__ ae_W, const float* __restrict__ ae_b)
{
    int m = blockIdx.x;          // token 0..3071
    int e = threadIdx.x;         // 0..255
    int b = m / TSEQ, t = m % TSEQ;
    int slot = t % 3, l = t / 3;

    const float *inp, *Wm, *bi; int dim;
    if (slot == 0)      { inp = goal;    Wm = ge_W; bi = ge_b; dim = 6; }
    else if (slot == 1) { inp = states;  Wm = se_W; bi = se_b; dim = 6; }
    else                { inp = actions; Wm = ae_W; bi = ae_b; dim = 3; }

    float v = bi[e];
    const float* ip = inp + (size_t)(b * LQ + l) * dim;
    #pragma unroll 6
    for (int i = 0; i < dim; i++) v += ip[i] * Wm[i * DM + e];

    int ts = timesteps[b * LQ + l];
    v += te_W[(size_t)ts * DM + e];
    g_u[(size_t)m * DM + e] = v;
}

// ---------------- per-row rmsnorm scale: rs[m] = rsqrt(mean(x^2)+eps) ----------------
__global__ void k_rowscale(const float* __restrict__ in, float* __restrict__ rs)
{
    int warp = blockIdx.x * 8 + (threadIdx.x >> 5);
    int lane = threadIdx.x & 31;
    const float4* p = (const float4*)(in + (size_t)warp * DM);
    float s = 0.f;
    #pragma unroll
    for (int i = lane; i < DM / 4; i += 32) {
        float4 v = p[i];
        s += v.x * v.x + v.y * v.y + v.z * v.z + v.w * v.w;
    }
    #pragma unroll
    for (int o = 16; o > 0; o >>= 1) s += __shfl_down_sync(0xffffffffu, s, o);
    if (lane == 0) rs[warp] = rsqrtf(s * (1.0f / DM) + 1e-5f);
}

// ---------------- 128x64x16 SGEMM, double-buffered smem, 8x4/thread -----------
// C[M,N] = A'[M,K] @ W[K,N]  where A' = A (NORM=false) or A * rs[m] * nw[k] (NORM=true)
// EPI: 0 = store (+bias if non-null), 1 = accumulate into C, 2 = atomicAdd (split-K)
// K is the K-slice length; blockIdx.z selects the slice.
template<int EPI, bool NORM>
__global__ __launch_bounds__(256)
void k_gemm128(const float* __restrict__ A, int lda,
               const float* __restrict__ W, int N, int K,
               const float* __restrict__ bias,
               const float* __restrict__ rs,
               const float* __restrict__ nw,
               float* __restrict__ C, int ldc)
{
    __shared__ float As[2][16][128];
    __shared__ float Ws[2][16][68];

    int tid = threadIdx.x;
    int bm = blockIdx.y * 128, bn = blockIdx.x * 64;
    int kb = blockIdx.z * K;
    int tx = tid & 15;       // col group -> cols tx*4 .. +4
    int ty = tid >> 4;       // row group -> rows ty*8 .. +8

    int arow = tid >> 2;            // 0..63
    int acol = (tid & 3) * 4;       // 0,4,8,12
    int wk = tid >> 4, wn = (tid & 15) * 4;

    float s0 = 1.f, s1 = 1.f;
    if (NORM) {
        s0 = rs[bm + arow];
        s1 = rs[bm + arow + 64];
    }

    const float* Ap0 = A + (size_t)(bm + arow) * lda + kb + acol;
    const float* Ap1 = Ap0 + (size_t)64 * lda;

    float4 pa0 = *(const float4*)(Ap0);
    float4 pa1 = *(const float4*)(Ap1);
    float4 pw  = *(const float4*)(W + (size_t)(kb + wk) * N + bn + wn);

    // stage tile 0 into buffer 0
    if (NORM) {
        float n0 = nw[acol + 0], n1 = nw[acol + 1];
        float n2 = nw[acol + 2], n3 = nw[acol + 3];
        As[0][acol + 0][arow] = pa0.x * s0 * n0;
        As[0][acol + 1][arow] = pa0.y * s0 * n1;
        As[0][acol + 2][arow] = pa0.z * s0 * n2;
        As[0][acol + 3][arow] = pa0.w * s0 * n3;
        As[0][acol + 0][arow + 64] = pa1.x * s1 * n0;
        As[0][acol + 1][arow + 64] = pa1.y * s1 * n1;
        As[0][acol + 2][arow + 64] = pa1.z * s1 * n2;
        As[0][acol + 3][arow + 64] = pa1.w * s1 * n3;
    } else {
        As[0][acol + 0][arow] = pa0.x;
        As[0][acol + 1][arow] = pa0.y;
        As[0][acol + 2][arow] = pa0.z;
        As[0][acol + 3][arow] = pa0.w;
        As[0][acol + 0][arow + 64] = pa1.x;
        As[0][acol + 1][arow + 64] = pa1.y;
        As[0][acol + 2][arow + 64] = pa1.z;
        As[0][acol + 3][arow + 64] = pa1.w;
    }
    *(float4*)&Ws[0][wk][wn] = pw;
    __syncthreads();

    float acc[8][4] = {};
    int buf = 0;

    for (int k0 = 0; k0 < K; k0 += 16) {
        bool has_next = (k0 + 16) < K;
        if (has_next) {
            pa0 = *(const float4*)(Ap0 + k0 + 16);
            pa1 = *(const float4*)(Ap1 + k0 + 16);
            pw  = *(const float4*)(W + (size_t)(kb + k0 + 16 + wk) * N + bn + wn);
        }

        #pragma unroll
        for (int k = 0; k < 16; k++) {
            float4 a0 = *(const float4*)&As[buf][k][ty * 8];
            float4 a1 = *(const float4*)&As[buf][k][ty * 8 + 4];
            float4 w0 = *(const float4*)&Ws[buf][k][tx * 4];
            float a[8] = {a0.x, a0.y, a0.z, a0.w, a1.x, a1.y, a1.z, a1.w};
            float w[4] = {w0.x, w0.y, w0.z, w0.w};
            #pragma unroll
            for (int i = 0; i < 8; i++)
                #pragma unroll
                for (int j = 0; j < 4; j++) acc[i][j] += a[i] * w[j];
        }

        if (has_next) {
            int nb = buf ^ 1;
            if (NORM) {
                float n0 = nw[k0 + 16 + acol + 0], n1 = nw[k0 + 16 + acol + 1];
                float n2 = nw[k0 + 16 + acol + 2], n3 = nw[k0 + 16 + acol + 3];
                As[nb][acol + 0][arow] = pa0.x * s0 * n0;
                As[nb][acol + 1][arow] = pa0.y * s0 * n1;
                As[nb][acol + 2][arow] = pa0.z * s0 * n2;
                As[nb][acol + 3][arow] = pa0.w * s0 * n3;
                As[nb][acol + 0][arow + 64] = pa1.x * s1 * n0;
                As[nb][acol + 1][arow + 64] = pa1.y * s1 * n1;
                As[nb][acol + 2][arow + 64] = pa1.z * s1 * n2;
                As[nb][acol + 3][arow + 64] = pa1.w * s1 * n3;
            } else {
                As[nb][acol + 0][arow] = pa0.x;
                As[nb][acol + 1][arow] = pa0.y;
                As[nb][acol + 2][arow] = pa0.z;
                As[nb][acol + 3][arow] = pa0.w;
                As[nb][acol + 0][arow + 64] = pa1.x;
                As[nb][acol + 1][arow + 64] = pa1.y;
                As[nb][acol + 2][arow + 64] = pa1.z;
                As[nb][acol + 3][arow + 64] = pa1.w;
            }
            *(float4*)&Ws[nb][wk][wn] = pw;
            __syncthreads();
            buf = nb;
        }
    }

    #pragma unroll
    for (int i = 0; i < 8; i++) {
        int row = bm + ty * 8 + i;
        #pragma unroll
        for (int j = 0; j < 4; j++) {
            int col = bn + tx * 4 + j;
            float v = acc[i][j];
            if (EPI == 0) {
                if (bias) v += bias[col];
                C[(size_t)row * ldc + col] = v;
            } else if (EPI == 1) {
                C[(size_t)row * ldc + col] += v;
            } else {
                atomicAdd(&C[(size_t)row * ldc + col], v);
            }
        }
    }
}

// ---------------- 64x64 split-K SGEMM (xproj, N=48), double-buffered ----------
__global__ __launch_bounds__(256)
void k_xproj(const float* __restrict__ A, int lda,
             const float* __restrict__ W, int N, int Ks,
             float* __restrict__ C, int ldc)
{
    __shared__ float As[2][16][64];
    __shared__ float Ws[2][16][68];

    int tid = threadIdx.x;
    int tx = tid & 15, ty = tid >> 4;
    int bm = blockIdx.y * 64, bn = blockIdx.x * 64;
    int kb = blockIdx.z * Ks;
    int arow = tid >> 2, acol = (tid & 3) << 2;
    int wn = tx * 4;
    bool wok = (bn + wn) < N;

    const float* Arow = A + (size_t)(bm + arow) * lda + acol;
    float4 pa = *(const float4*)(Arow + kb);
    float4 pw = make_float4(0.f, 0.f, 0.f, 0.f);
    if (wok) pw = *(const float4*)(W + (size_t)(kb + ty) * N + bn + wn);

    As[0][acol + 0][arow] = pa.x;
    As[0][acol + 1][arow] = pa.y;
    As[0][acol + 2][arow] = pa.z;
    As[0][acol + 3][arow] = pa.w;
    *(float4*)&Ws[0][ty][wn] = pw;
    __syncthreads();

    float acc[4][4] = {};
    int buf = 0;

    for (int k0 = kb; k0 < kb + Ks; k0 += 16) {
        bool has_next = (k0 + 16) < kb + Ks;
        if (has_next) {
            pa = *(const float4*)(Arow + k0 + 16);
            if (wok) pw = *(const float4*)(W + (size_t)(k0 + 16 + ty) * N + bn + wn);
        }

        #pragma unroll
        for (int k = 0; k < 16; k++) {
            float4 a0 = *(const float4*)&As[buf][k][ty * 4];
            float4 w0 = *(const float4*)&Ws[buf][k][tx * 4];
            float a[4] = {a0.x, a0.y, a0.z, a0.w};
            float w[4] = {w0.x, w0.y, w0.z, w0.w};
            #pragma unroll
            for (int i = 0; i < 4; i++)
                #pragma unroll
                for (int j = 0; j < 4; j++) acc[i][j] += a[i] * w[j];
        }

        if (has_next) {
            int nb = buf ^ 1;
            As[nb][acol + 0][arow] = pa.x;
            As[nb][acol + 1][arow] = pa.y;
            As[nb][acol + 2][arow] = pa.z;
            As[nb][acol + 3][arow] = pa.w;
            *(float4*)&Ws[nb][ty][wn] = pw;
            __syncthreads();
            buf = nb;
        }
    }

    #pragma unroll
    for (int i = 0; i < 4; i++) {
        int row = bm + ty * 4 + i;
        #pragma unroll
        for (int j = 0; j < 4; j++) {
            int col = bn + tx * 4 + j;
            if (col < N) atomicAdd(&C[(size_t)row * ldc + col], acc[i][j]);
        }
    }
}

// ---------------- causal depthwise conv (k=4) + silu, 4 tokens/thread ----------
// Also zeroes g_proj for the split-K xproj that follows.
__global__ void k_conv(const float* __restrict__ cw, const float* __restrict__ cb)
{
    int idx = blockIdx.x * blockDim.x + threadIdx.x;  // over (MTOK/4)*(DI/4)=98304
    {
        if (idx < MTOK * 48) g_proj[idx] = 0.f;
        int i2 = idx + 98304;
        if (i2 < MTOK * 48) g_proj[i2] = 0.f;
    }
    if (idx >= (MTOK / 4) * (DI / 4)) return;
    int mg = idx / (DI / 4), dv = idx % (DI / 4);
    int d = dv * 4;
    int b = mg / (TSEQ / 4), tg = mg % (TSEQ / 4);
    int t0 = tg * 4;

    float4 win[7];
    #pragma unroll
    for (int j = 0; j < 7; j++) {
        int tt = t0 - 3 + j;
        win[j] = (tt >= 0)
            ? *(const float4*)(g_xz + (size_t)(b * TSEQ + tt) * (2 * DI) + d)
            : make_float4(0.f, 0.f, 0.f, 0.f);
    }

    float4 cw0 = *(const float4*)(cw + (d + 0) * 4);
    float4 cw1 = *(const float4*)(cw + (d + 1) * 4);
    float4 cw2 = *(const float4*)(cw + (d + 2) * 4);
    float4 cw3 = *(const float4*)(cw + (d + 3) * 4);
    float4 cb4 = *(const float4*)(cb + d);

    float cwk[4][4] = {{cw0.x, cw0.y, cw0.z, cw0.w},
                       {cw1.x, cw1.y, cw1.z, cw1.w},
                       {cw2.x, cw2.y, cw2.z, cw2.w},
                       {cw3.x, cw3.y, cw3.z, cw3.w}};

    #pragma unroll
    for (int j2 = 0; j2 < 4; j2++) {
        float4 acc = cb4;
        #pragma unroll
        for (int k = 0; k < 4; k++) {
            float4 v = win[j2 + k];
            acc.x += cwk[0][k] * v.x;
            acc.y += cwk[1][k] * v.y;
            acc.z += cwk[2][k] * v.z;
            acc.w += cwk[3][k] * v.w;
        }
        acc.x = acc.x / (1.f + __expf(-acc.x));
        acc.y = acc.y / (1.f + __expf(-acc.y));
        acc.z = acc.z / (1.f + __expf(-acc.z));
        acc.w = acc.w / (1.f + __expf(-acc.w));
        *(float4*)(g_xc + (size_t)(b * TSEQ + t0 + j2) * DI + d) = acc;
    }
}

// ---------------- selective scan: recurrence-only serial loop -----------------
__global__ __launch_bounds__(64)
void k_scan(const float* __restrict__ A_log, const float* __restrict__ Dp,
            const float* __restrict__ dtW, const float* __restrict__ dtb)
{
    int b = blockIdx.x >> 3;                          // batch
    int d = ((blockIdx.x & 7) << 6) + threadIdx.x;    // 0..511

    float A[16], h[16];
    #pragma unroll
    for (int n = 0; n < 16; n++) {
        A[n] = -__expf(A_log[d * 16 + n]);
        h[n] = 0.f;
    }
    float A0 = A[0];
    bool lin = true;
    #pragma unroll
    for (int n = 0; n < 16; n++)
        lin = lin && (fabsf(A[n] - (float)(n + 1) * A0) <= 1e-4f * fabsf(A[n]));

    float W16[16];
    #pragma unroll
    for (int r = 0; r < 16; r++) W16[r] = dtW[r * DI + d];
    float bd = dtb[d], Dd = Dp[d];

    __shared__ float sp[8][48];   // 8 steps of (dt_in[16], B[16], C[16])

    for (int t0 = 0; t0 < TSEQ; t0 += 8) {
        __syncthreads();
        int i0 = threadIdx.x * 6;                     // 64*6 = 384 floats
        #pragma unroll
        for (int i = 0; i < 6; i++) {
            int idx = i0 + i; int st = idx / 48, j = idx % 48;
            sp[st][j] = g_proj[((size_t)(b * TSEQ + t0 + st)) * 48 + j];
        }
        float xc8[8], z8[8];
        #pragma unroll
        for (int i = 0; i < 8; i++)
            xc8[i] = g_xc[(size_t)(b * TSEQ + t0 + i) * DI + d];
        #pragma unroll
        for (int i = 0; i < 8; i++)
            z8[i] = g_xz[(size_t)(b * TSEQ + t0 + i) * (2 * DI) + DI + d];
        __syncthreads();

        float dtx8[8], p8[8], gz8[8], xD8[8];
        #pragma unroll
        for (int tt = 0; tt < 8; tt++) {
            float dtr = bd;
            #pragma unroll
            for (int r = 0; r < 16; r++) dtr += sp[tt][r] * W16[r];
            float dt = (dtr > 15.f) ? dtr : log1pf(__expf(dtr));
            float x = xc8[tt];
            dtx8[tt] = dt * x;
            p8[tt] = lin ? __expf(dt * A0) : dt;
            float z = z8[tt];
            gz8[tt] = z / (1.f + __expf(-z));
            xD8[tt] = x * Dd;
        }

        #pragma unroll
        for (int tt = 0; tt < 8; tt++) {
            float dA[16];
            if (lin) {
                float p = p8[tt], p2 = p * p;
                float c1 = p, c2 = p2;
                dA[0] = c1; dA[1] = c2;
                #pragma unroll
                for (int j = 2; j < 16; j += 2) {
                    c1 *= p2; c2 *= p2;
                    dA[j] = c1; dA[j + 1] = c2;
                }
            } else {
                #pragma unroll
                for (int n = 0; n < 16; n++) dA[n] = __expf(p8[tt] * A[n]);
            }

            float dtx = dtx8[tt];
            float y0 = 0.f, y1 = 0.f, y2 = 0.f, y3 = 0.f;
            #pragma unroll
            for (int n = 0; n < 16; n += 4) {
                h[n + 0] = dA[n + 0] * h[n + 0] + dtx * sp[tt][16 + n + 0];
                h[n + 1] = dA[n + 1] * h[n + 1] + dtx * sp[tt][16 + n + 1];
                h[n + 2] = dA[n + 2] * h[n + 2] + dtx * sp[tt][16 + n + 2];
                h[n + 3] = dA[n + 3] * h[n + 3] + dtx * sp[tt][16 + n + 3];
                y0 += h[n + 0] * sp[tt][32 + n + 0];
                y1 += h[n + 1] * sp[tt][32 + n + 1];
                y2 += h[n + 2] * sp[tt][32 + n + 2];
                y3 += h[n + 3] * sp[tt][32 + n + 3];
            }
            float y = (y0 + y1) + (y2 + y3);
            g_y[(size_t)(b * TSEQ + t0 + tt) * DI + d] = (y + xD8[tt]) * gz8[tt];
        }
    }
}

// ---------------- heads with fused final rmsnorm (via rs) ----------------
__global__ void k_heads(const float* __restrict__ fnw, const float* __restrict__ rs,
                        const float* __restrict__ ps_W, const float* __restrict__ ps_b,
                        const float* __restrict__ pa_W, const float* __restrict__ pa_b,
                        float* __restrict__ out)
{
    int idx = blockIdx.x * blockDim.x + threadIdx.x;
    if (idx >= 6144 + 3072) return;
    if (idx < 6144) {
        int j = idx % 6; int l = (idx / 6) % LQ; int b = idx / (6 * LQ);
        int m = b * TSEQ + l * 3 + 2;   // action-slot tokens -> state preds
        float acc = 0.f;
        const float* f = g_res + (size_t)m * DM;
        #pragma unroll 8
        for (int e = 0; e < DM; e++) acc += f[e] * fnw[e] * ps_W[e * 6 + j];
        out[idx] = acc * rs[m] + ps_b[j];
    } else {
        int k = idx - 6144;
        int j = k % 3; int l = (k / 3) % LQ; int b = k / (3 * LQ);
        int m = b * TSEQ + l * 3 + 1;   // state-slot tokens -> action preds
        float acc = 0.f;
        const float* f = g_res + (size_t)m * DM;
        #pragma unroll 8
        for (int e = 0; e < DM; e++) acc += f[e] * fnw[e] * pa_W[e * 3 + j];
        out[idx] = tanhf(acc * rs[m] + pa_b[j]);
    }
}

// ---------------- launch ----------------
extern "C" void kernel_launch(void* const* d_in, const int* in_sizes, int n_in,
                              void* d_out, int out_size)
{
    const float* states    = (const float*)d_in[0];
    const float* actions   = (const float*)d_in[1];
    const float* goal      = (const float*)d_in[2];
    const int*   timesteps = (const int*)  d_in[3];
    const float* te_W      = (const float*)d_in[4];
    const float* se_W      = (const float*)d_in[5];
    const float* se_b      = (const float*)d_in[6];
    const float* ge_W      = (const float*)d_in[7];
    const float* ge_b      = (const float*)d_in[8];
    const float* ae_W      = (const float*)d_in[9];
    const float* ae_b      = (const float*)d_in[10];
    const float* bb_in_W   = (const float*)d_in[11];
    const float* bb_in_b   = (const float*)d_in[12];
    const float* norm_w    = (const float*)d_in[13];
    const float* in_proj_W = (const float*)d_in[14];
    const float* conv_w    = (const float*)d_in[15];
    const float* conv_b    = (const float*)d_in[16];
    const float* xproj_W   = (const float*)d_in[17];
    const float* dt_W      = (const float*)d_in[18];
    const float* dt_b      = (const float*)d_in[19];
    const float* A_log     = (const float*)d_in[20];
    const float* Dp        = (const float*)d_in[21];
    const float* out_W     = (const float*)d_in[22];
    const float* fnorm_w   = (const float*)d_in[23];
    const float* ps_W      = (const float*)d_in[24];
    const float* ps_b      = (const float*)d_in[25];
    const float* pa_W      = (const float*)d_in[26];
    const float* pa_b      = (const float*)d_in[27];
    float* out = (float*)d_out;

    float *pu, *pres, *prs, *pxz, *pxc, *pproj, *py;
    cudaGetSymbolAddress((void**)&pu,    g_u);
    cudaGetSymbolAddress((void**)&pres,  g_res);
    cudaGetSymbolAddress((void**)&prs,   g_rs);
    cudaGetSymbolAddress((void**)&pxz,   g_xz);
    cudaGetSymbolAddress((void**)&pxc,   g_xc);
    cudaGetSymbolAddress((void**)&pproj, g_proj);
    cudaGetSymbolAddress((void**)&py,    g_y);

    // 1) embeddings -> u
    k_embed<<<MTOK, DM>>>(states, actions, goal, timesteps, te_W,
                          se_W, se_b, ge_W, ge_b, ae_W, ae_b);

    // 2) residual = u @ bb_in_W + bb_in_b   (3072 x 256 x 256)
    k_gemm128<0, false><<<dim3(DM / 64, MTOK / 128, 1), 256>>>(
        pu, DM, bb_in_W, DM, DM, bb_in_b, nullptr, nullptr, pres, DM);

    // 3) mamba layers
    for (int i = 0; i < NL; i++) {
        const float* inW  = in_proj_W + (size_t)i * DM * 2 * DI;
        const float* cw   = conv_w    + (size_t)i * DI * 4;
        const float* cb   = conv_b    + (size_t)i * DI;
        const float* xpW  = xproj_W   + (size_t)i * DI * 48;
        const float* dtW  = dt_W      + (size_t)i * RK * DI;
        const float* dtb  = dt_b      + (size_t)i * DI;
        const float* Al   = A_log     + (size_t)i * DI * DS;
        const float* Dpi  = Dp        + (size_t)i * DI;
        const float* oW   = out_W     + (size_t)i * DI * DM;
        const float* nw   = norm_w    + (size_t)i * DM;

        // rmsnorm row scales
        k_rowscale<<<MTOK / 8, 256>>>(pres, prs);

        // xz = rmsnorm(res) @ in_W   (3072 x 1024 x 256), norm folded into A-load
        k_gemm128<0, true><<<dim3(2 * DI / 64, MTOK / 128, 1), 256>>>(
            pres, DM, inW, 2 * DI, DM, nullptr, prs, nw, pxz, 2 * DI);

        // causal depthwise conv + silu -> xc ; zero proj
        k_conv<<<((MTOK / 4) * (DI / 4)) / 256, 256>>>(cw, cb);

        // proj = xc @ xproj_W  (3072 x 48 x 512), split-K x4, atomic accumulate
        k_xproj<<<dim3(1, MTOK / 64, 4), 256>>>(pxc, DI, xpW, 48, DI / 4, pproj, 48);

        // selective scan (fused dt-GEMM + softplus + gate) -> y
        k_scan<<<BQ * 8, 64>>>(Al, Dpi, dtW, dtb);

        // residual += y @ out_W   (3072 x 256 x 512), split-K x2, atomic accumulate
        k_gemm128<2, false><<<dim3(DM / 64, MTOK / 128, 2), 256>>>(
            py, DI, oW, DM, DI / 2, nullptr, nullptr, nullptr, pres, DM);
    }

    // 4) final rmsnorm scales + fused heads
    k_rowscale<<<MTOK / 8, 256>>>(pres, prs);
    k_heads<<<(9216 + 255) / 256, 256>>>(fnorm_w, prs, ps_W, ps_b, pa_W, pa_b, out);
}

// round 17
// speedup vs baseline: 1.8820x; 1.8820x over previous
#include <cuda_runtime.h>
#include <math.h>

// ---------------- problem constants ----------------
#define BQ   8
#define LQ   128
#define TSEQ 384          // 3 * L tokens per batch
#define MTOK 3072         // BQ * TSEQ
#define DM   256          // d_model
#define DI   512          // d_inner
#define DS   16           // d_state
#define RK   16           // dt_rank
#define NL   4

// ---------------- scratch (device globals; no allocation allowed) ----------------
__device__ float g_u  [MTOK * DM];
__device__ float g_res[MTOK * DM];
__device__ float g_rs [MTOK];          // per-row rmsnorm scales
__device__ float g_xz [MTOK * 2 * DI];
__device__ float g_xc [MTOK * DI];
__device__ float g_proj[MTOK * 48];
__device__ float g_y  [MTOK * DI];

// ---------------- tf32 helpers ----------------
__device__ __forceinline__ unsigned f2tf32(float x)
{
    unsigned u;
    asm("cvt.rna.tf32.f32 %0, %1;" : "=r"(u) : "f"(x));
    return u;
}
__device__ __forceinline__ void mma_tf32(float* d, const unsigned* a, const unsigned* b)
{
    asm volatile(
        "mma.sync.aligned.m16n8k8.row.col.f32.tf32.tf32.f32 "
        "{%0,%1,%2,%3}, {%4,%5,%6,%7}, {%8,%9}, {%0,%1,%2,%3};"
        : "+f"(d[0]), "+f"(d[1]), "+f"(d[2]), "+f"(d[3])
        : "r"(a[0]), "r"(a[1]), "r"(a[2]), "r"(a[3]), "r"(b[0]), "r"(b[1]));
}

// ---------------- embeddings + interleave -> u ----------------
__global__ void k_embed(const float* __restrict__ states,
                        const float* __restrict__ actions,
                        const float* __restrict__ goal,
                        const int*   __restrict__ timesteps,
                        const float* __restrict__ te_W,
                        const float* __restrict__ se_W, const float* __restrict__ se_b,
                        const float* __restrict__ ge_W, const float* __restrict__ ge_b,
                        const float* __restrict__ ae_W, const float* __restrict__ ae_b)
{
    int m = blockIdx.x;          // token 0..3071
    int e = threadIdx.x;         // 0..255
    int b = m / TSEQ, t = m % TSEQ;
    int slot = t % 3, l = t / 3;

    const float *inp, *Wm, *bi; int dim;
    if (slot == 0)      { inp = goal;    Wm = ge_W; bi = ge_b; dim = 6; }
    else if (slot == 1) { inp = states;  Wm = se_W; bi = se_b; dim = 6; }
    else                { inp = actions; Wm = ae_W; bi = ae_b; dim = 3; }

    float v = bi[e];
    const float* ip = inp + (size_t)(b * LQ + l) * dim;
    #pragma unroll 6
    for (int i = 0; i < dim; i++) v += ip[i] * Wm[i * DM + e];

    int ts = timesteps[b * LQ + l];
    v += te_W[(size_t)ts * DM + e];
    g_u[(size_t)m * DM + e] = v;
}

// ---------------- per-row rmsnorm scale ----------------
__global__ void k_rowscale(const float* __restrict__ in, float* __restrict__ rs)
{
    int warp = blockIdx.x * 8 + (threadIdx.x >> 5);
    int lane = threadIdx.x & 31;
    const float4* p = (const float4*)(in + (size_t)warp * DM);
    float s = 0.f;
    #pragma unroll
    for (int i = lane; i < DM / 4; i += 32) {
        float4 v = p[i];
        s += v.x * v.x + v.y * v.y + v.z * v.z + v.w * v.w;
    }
    #pragma unroll
    for (int o = 16; o > 0; o >>= 1) s += __shfl_down_sync(0xffffffffu, s, o);
    if (lane == 0) rs[warp] = rsqrtf(s * (1.0f / DM) + 1e-5f);
}

// ---------------- fp32 128x64 SGEMM (bb_in only; proven R11 body) --------------
__global__ __launch_bounds__(256)
void k_gemm_f32(const float* __restrict__ A, int lda,
                const float* __restrict__ W, int N, int K,
                const float* __restrict__ bias,
                float* __restrict__ C, int ldc)
{
    __shared__ float As[16][128];
    __shared__ float Ws[16][68];

    int tid = threadIdx.x;
    int bm = blockIdx.y * 128, bn = blockIdx.x * 64;
    int tx = tid & 15, ty = tid >> 4;
    int arow = tid >> 2, acol = (tid & 3) * 4;
    int wk = tid >> 4, wn = (tid & 15) * 4;

    const float* Ap0 = A + (size_t)(bm + arow) * lda + acol;
    const float* Ap1 = Ap0 + (size_t)64 * lda;

    float4 pa0 = *(const float4*)(Ap0);
    float4 pa1 = *(const float4*)(Ap1);
    float4 pw  = *(const float4*)(W + (size_t)wk * N + bn + wn);

    float acc[8][4] = {};

    for (int k0 = 0; k0 < K; k0 += 16) {
        __syncthreads();
        As[acol + 0][arow] = pa0.x;
        As[acol + 1][arow] = pa0.y;
        As[acol + 2][arow] = pa0.z;
        As[acol + 3][arow] = pa0.w;
        As[acol + 0][arow + 64] = pa1.x;
        As[acol + 1][arow + 64] = pa1.y;
        As[acol + 2][arow + 64] = pa1.z;
        As[acol + 3][arow + 64] = pa1.w;
        *(float4*)&Ws[wk][wn] = pw;
        __syncthreads();

        if (k0 + 16 < K) {
            pa0 = *(const float4*)(Ap0 + k0 + 16);
            pa1 = *(const float4*)(Ap1 + k0 + 16);
            pw  = *(const float4*)(W + (size_t)(k0 + 16 + wk) * N + bn + wn);
        }

        #pragma unroll
        for (int k = 0; k < 16; k++) {
            float4 a0 = *(const float4*)&As[k][ty * 8];
            float4 a1 = *(const float4*)&As[k][ty * 8 + 4];
            float4 w0 = *(const float4*)&Ws[k][tx * 4];
            float a[8] = {a0.x, a0.y, a0.z, a0.w, a1.x, a1.y, a1.z, a1.w};
            float w[4] = {w0.x, w0.y, w0.z, w0.w};
            #pragma unroll
            for (int i = 0; i < 8; i++)
                #pragma unroll
                for (int j = 0; j < 4; j++) acc[i][j] += a[i] * w[j];
        }
    }

    #pragma unroll
    for (int i = 0; i < 8; i++) {
        int row = bm + ty * 8 + i;
        #pragma unroll
        for (int j = 0; j < 4; j++) {
            int col = bn + tx * 4 + j;
            float v = acc[i][j];
            if (bias) v += bias[col];
            C[(size_t)row * ldc + col] = v;
        }
    }
}

// ---------------- TF32 128x64 tensor-core GEMM -------------------------------
// C[M,N] = A'[M,K] @ W[K,N] ; A' = A (NORM=false) or A * rs[m] * nw[k] (NORM=true)
// EPI: 0 = store, 2 = atomicAdd (split-K; blockIdx.z picks K-slice of length K)
// 8 warps: warp grid 4(M) x 2(N); each warp computes 32x32 via m16n8k8 mma.
template<int EPI, bool NORM>
__global__ __launch_bounds__(256)
void k_tgemm(const float* __restrict__ A, int lda,
             const float* __restrict__ W, int N, int K,
             const float* __restrict__ rs,
             const float* __restrict__ nw,
             float* __restrict__ C, int ldc)
{
    __shared__ unsigned As[16 * 132];   // [k][m], stride 132 -> conflict-free frags
    __shared__ unsigned Ws[16 * 68];    // [k][n], stride 68

    int tid = threadIdx.x;
    int bm = blockIdx.y * 128, bn = blockIdx.x * 64;
    int kb = blockIdx.z * K;

    int lane = tid & 31, warp = tid >> 5;
    int wm = (warp & 3) * 32;           // warp M offset (0,32,64,96)
    int wnW = (warp >> 2) * 32;         // warp N offset (0,32)
    int g = lane >> 2, tig = lane & 3;

    int arow = tid >> 2, acol = (tid & 3) * 4;
    int wk = tid >> 4, wn = (tid & 15) * 4;

    float s0 = 1.f, s1 = 1.f;
    if (NORM) { s0 = rs[bm + arow]; s1 = rs[bm + arow + 64]; }

    const float* Ap0 = A + (size_t)(bm + arow) * lda + kb + acol;
    const float* Ap1 = Ap0 + (size_t)64 * lda;

    float4 pa0 = *(const float4*)(Ap0);
    float4 pa1 = *(const float4*)(Ap1);
    float4 pw  = *(const float4*)(W + (size_t)(kb + wk) * N + bn + wn);

    float acc[2][4][4];
    #pragma unroll
    for (int mi = 0; mi < 2; mi++)
        #pragma unroll
        for (int ni = 0; ni < 4; ni++)
            #pragma unroll
            for (int q = 0; q < 4; q++) acc[mi][ni][q] = 0.f;

    for (int k0 = 0; k0 < K; k0 += 16) {
        __syncthreads();
        if (NORM) {
            float n0 = nw[k0 + acol + 0], n1 = nw[k0 + acol + 1];
            float n2 = nw[k0 + acol + 2], n3 = nw[k0 + acol + 3];
            As[(acol + 0) * 132 + arow] = f2tf32(pa0.x * s0 * n0);
            As[(acol + 1) * 132 + arow] = f2tf32(pa0.y * s0 * n1);
            As[(acol + 2) * 132 + arow] = f2tf32(pa0.z * s0 * n2);
            As[(acol + 3) * 132 + arow] = f2tf32(pa0.w * s0 * n3);
            As[(acol + 0) * 132 + arow + 64] = f2tf32(pa1.x * s1 * n0);
            As[(acol + 1) * 132 + arow + 64] = f2tf32(pa1.y * s1 * n1);
            As[(acol + 2) * 132 + arow + 64] = f2tf32(pa1.z * s1 * n2);
            As[(acol + 3) * 132 + arow + 64] = f2tf32(pa1.w * s1 * n3);
        } else {
            As[(acol + 0) * 132 + arow] = f2tf32(pa0.x);
            As[(acol + 1) * 132 + arow] = f2tf32(pa0.y);
            As[(acol + 2) * 132 + arow] = f2tf32(pa0.z);
            As[(acol + 3) * 132 + arow] = f2tf32(pa0.w);
            As[(acol + 0) * 132 + arow + 64] = f2tf32(pa1.x);
            As[(acol + 1) * 132 + arow + 64] = f2tf32(pa1.y);
            As[(acol + 2) * 132 + arow + 64] = f2tf32(pa1.z);
            As[(acol + 3) * 132 + arow + 64] = f2tf32(pa1.w);
        }
        Ws[wk * 68 + wn + 0] = f2tf32(pw.x);
        Ws[wk * 68 + wn + 1] = f2tf32(pw.y);
        Ws[wk * 68 + wn + 2] = f2tf32(pw.z);
        Ws[wk * 68 + wn + 3] = f2tf32(pw.w);
        __syncthreads();

        if (k0 + 16 < K) {
            pa0 = *(const float4*)(Ap0 + k0 + 16);
            pa1 = *(const float4*)(Ap1 + k0 + 16);
            pw  = *(const float4*)(W + (size_t)(kb + k0 + 16 + wk) * N + bn + wn);
        }

        #pragma unroll
        for (int ks = 0; ks < 16; ks += 8) {
            unsigned af[2][4], bf[4][2];
            #pragma unroll
            for (int mi = 0; mi < 2; mi++) {
                int r0 = wm + mi * 16 + g;
                af[mi][0] = As[(ks + tig)     * 132 + r0];
                af[mi][1] = As[(ks + tig)     * 132 + r0 + 8];
                af[mi][2] = As[(ks + tig + 4) * 132 + r0];
                af[mi][3] = As[(ks + tig + 4) * 132 + r0 + 8];
            }
            #pragma unroll
            for (int ni = 0; ni < 4; ni++) {
                int c0 = wnW + ni * 8 + g;
                bf[ni][0] = Ws[(ks + tig)     * 68 + c0];
                bf[ni][1] = Ws[(ks + tig + 4) * 68 + c0];
            }
            #pragma unroll
            for (int mi = 0; mi < 2; mi++)
                #pragma unroll
                for (int ni = 0; ni < 4; ni++)
                    mma_tf32(acc[mi][ni], af[mi], bf[ni]);
        }
    }

    #pragma unroll
    for (int mi = 0; mi < 2; mi++) {
        int r0 = bm + wm + mi * 16 + g;
        #pragma unroll
        for (int ni = 0; ni < 4; ni++) {
            int cb = bn + wnW + ni * 8 + 2 * tig;
            if (EPI == 0) {
                C[(size_t)r0 * ldc + cb]           = acc[mi][ni][0];
                C[(size_t)r0 * ldc + cb + 1]       = acc[mi][ni][1];
                C[(size_t)(r0 + 8) * ldc + cb]     = acc[mi][ni][2];
                C[(size_t)(r0 + 8) * ldc + cb + 1] = acc[mi][ni][3];
            } else {
                atomicAdd(&C[(size_t)r0 * ldc + cb],           acc[mi][ni][0]);
                atomicAdd(&C[(size_t)r0 * ldc + cb + 1],       acc[mi][ni][1]);
                atomicAdd(&C[(size_t)(r0 + 8) * ldc + cb],     acc[mi][ni][2]);
                atomicAdd(&C[(size_t)(r0 + 8) * ldc + cb + 1], acc[mi][ni][3]);
            }
        }
    }
}

// ---------------- 64x64 split-K SGEMM (xproj, N=48), atomic epilogue ----------
__global__ __launch_bounds__(256)
void k_xproj(const float* __restrict__ A, int lda,
             const float* __restrict__ W, int N, int Ks,
             float* __restrict__ C, int ldc)
{
    __shared__ float As[16][64];
    __shared__ float Ws[16][68];

    int tid = threadIdx.x;
    int tx = tid & 15, ty = tid >> 4;
    int bm = blockIdx.y * 64, bn = blockIdx.x * 64;
    int kb = blockIdx.z * Ks;
    int arow = tid >> 2, acol = (tid & 3) << 2;
    int wn = tx * 4;
    bool wok = (bn + wn) < N;

    const float* Arow = A + (size_t)(bm + arow) * lda + acol;
    float4 pa = *(const float4*)(Arow + kb);
    float4 pw = make_float4(0.f, 0.f, 0.f, 0.f);
    if (wok) pw = *(const float4*)(W + (size_t)(kb + ty) * N + bn + wn);

    float acc[4][4] = {};

    for (int k0 = kb; k0 < kb + Ks; k0 += 16) {
        __syncthreads();
        As[acol + 0][arow] = pa.x;
        As[acol + 1][arow] = pa.y;
        As[acol + 2][arow] = pa.z;
        As[acol + 3][arow] = pa.w;
        *(float4*)&Ws[ty][wn] = pw;
        __syncthreads();

        if (k0 + 16 < kb + Ks) {
            pa = *(const float4*)(Arow + k0 + 16);
            if (wok) pw = *(const float4*)(W + (size_t)(k0 + 16 + ty) * N + bn + wn);
        }

        #pragma unroll
        for (int k = 0; k < 16; k++) {
            float4 a0 = *(const float4*)&As[k][ty * 4];
            float4 w0 = *(const float4*)&Ws[k][tx * 4];
            float a[4] = {a0.x, a0.y, a0.z, a0.w};
            float w[4] = {w0.x, w0.y, w0.z, w0.w};
            #pragma unroll
            for (int i = 0; i < 4; i++)
                #pragma unroll
                for (int j = 0; j < 4; j++) acc[i][j] += a[i] * w[j];
        }
    }

    #pragma unroll
    for (int i = 0; i < 4; i++) {
        int row = bm + ty * 4 + i;
        #pragma unroll
        for (int j = 0; j < 4; j++) {
            int col = bn + tx * 4 + j;
            if (col < N) atomicAdd(&C[(size_t)row * ldc + col], acc[i][j]);
        }
    }
}

// ---------------- causal depthwise conv (k=4) + silu, 4 tokens/thread ----------
__global__ void k_conv(const float* __restrict__ cw, const float* __restrict__ cb)
{
    int idx = blockIdx.x * blockDim.x + threadIdx.x;  // over (MTOK/4)*(DI/4)=98304
    {
        if (idx < MTOK * 48) g_proj[idx] = 0.f;
        int i2 = idx + 98304;
        if (i2 < MTOK * 48) g_proj[i2] = 0.f;
    }
    if (idx >= (MTOK / 4) * (DI / 4)) return;
    int mg = idx / (DI / 4), dv = idx % (DI / 4);
    int d = dv * 4;
    int b = mg / (TSEQ / 4), tg = mg % (TSEQ / 4);
    int t0 = tg * 4;

    float4 win[7];
    #pragma unroll
    for (int j = 0; j < 7; j++) {
        int tt = t0 - 3 + j;
        win[j] = (tt >= 0)
            ? *(const float4*)(g_xz + (size_t)(b * TSEQ + tt) * (2 * DI) + d)
            : make_float4(0.f, 0.f, 0.f, 0.f);
    }

    float4 cw0 = *(const float4*)(cw + (d + 0) * 4);
    float4 cw1 = *(const float4*)(cw + (d + 1) * 4);
    float4 cw2 = *(const float4*)(cw + (d + 2) * 4);
    float4 cw3 = *(const float4*)(cw + (d + 3) * 4);
    float4 cb4 = *(const float4*)(cb + d);

    float cwk[4][4] = {{cw0.x, cw0.y, cw0.z, cw0.w},
                       {cw1.x, cw1.y, cw1.z, cw1.w},
                       {cw2.x, cw2.y, cw2.z, cw2.w},
                       {cw3.x, cw3.y, cw3.z, cw3.w}};

    #pragma unroll
    for (int j2 = 0; j2 < 4; j2++) {
        float4 acc = cb4;
        #pragma unroll
        for (int k = 0; k < 4; k++) {
            float4 v = win[j2 + k];
            acc.x += cwk[0][k] * v.x;
            acc.y += cwk[1][k] * v.y;
            acc.z += cwk[2][k] * v.z;
            acc.w += cwk[3][k] * v.w;
        }
        acc.x = acc.x / (1.f + __expf(-acc.x));
        acc.y = acc.y / (1.f + __expf(-acc.y));
        acc.z = acc.z / (1.f + __expf(-acc.z));
        acc.w = acc.w / (1.f + __expf(-acc.w));
        *(float4*)(g_xc + (size_t)(b * TSEQ + t0 + j2) * DI + d) = acc;
    }
}

// ---------------- selective scan: recurrence-only serial loop -----------------
__global__ __launch_bounds__(64)
void k_scan(const float* __restrict__ A_log, const float* __restrict__ Dp,
            const float* __restrict__ dtW, const float* __restrict__ dtb)
{
    int b = blockIdx.x >> 3;
    int d = ((blockIdx.x & 7) << 6) + threadIdx.x;

    float A[16], h[16];
    #pragma unroll
    for (int n = 0; n < 16; n++) {
        A[n] = -__expf(A_log[d * 16 + n]);
        h[n] = 0.f;
    }
    float A0 = A[0];
    bool lin = true;
    #pragma unroll
    for (int n = 0; n < 16; n++)
        lin = lin && (fabsf(A[n] - (float)(n + 1) * A0) <= 1e-4f * fabsf(A[n]));

    float W16[16];
    #pragma unroll
    for (int r = 0; r < 16; r++) W16[r] = dtW[r * DI + d];
    float bd = dtb[d], Dd = Dp[d];

    __shared__ float sp[8][48];

    for (int t0 = 0; t0 < TSEQ; t0 += 8) {
        __syncthreads();
        int i0 = threadIdx.x * 6;
        #pragma unroll
        for (int i = 0; i < 6; i++) {
            int idx = i0 + i; int st = idx / 48, j = idx % 48;
            sp[st][j] = g_proj[((size_t)(b * TSEQ + t0 + st)) * 48 + j];
        }
        float xc8[8], z8[8];
        #pragma unroll
        for (int i = 0; i < 8; i++)
            xc8[i] = g_xc[(size_t)(b * TSEQ + t0 + i) * DI + d];
        #pragma unroll
        for (int i = 0; i < 8; i++)
            z8[i] = g_xz[(size_t)(b * TSEQ + t0 + i) * (2 * DI) + DI + d];
        __syncthreads();

        float dtx8[8], p8[8], gz8[8], xD8[8];
        #pragma unroll
        for (int tt = 0; tt < 8; tt++) {
            float dtr = bd;
            #pragma unroll
            for (int r = 0; r < 16; r++) dtr += sp[tt][r] * W16[r];
            float dt = (dtr > 15.f) ? dtr : log1pf(__expf(dtr));
            float x = xc8[tt];
            dtx8[tt] = dt * x;
            p8[tt] = lin ? __expf(dt * A0) : dt;
            float z = z8[tt];
            gz8[tt] = z / (1.f + __expf(-z));
            xD8[tt] = x * Dd;
        }

        #pragma unroll
        for (int tt = 0; tt < 8; tt++) {
            float dA[16];
            if (lin) {
                float p = p8[tt], p2 = p * p;
                float c1 = p, c2 = p2;
                dA[0] = c1; dA[1] = c2;
                #pragma unroll
                for (int j = 2; j < 16; j += 2) {
                    c1 *= p2; c2 *= p2;
                    dA[j] = c1; dA[j + 1] = c2;
                }
            } else {
                #pragma unroll
                for (int n = 0; n < 16; n++) dA[n] = __expf(p8[tt] * A[n]);
            }

            float dtx = dtx8[tt];
            float y0 = 0.f, y1 = 0.f, y2 = 0.f, y3 = 0.f;
            #pragma unroll
            for (int n = 0; n < 16; n += 4) {
                h[n + 0] = dA[n + 0] * h[n + 0] + dtx * sp[tt][16 + n + 0];
                h[n + 1] = dA[n + 1] * h[n + 1] + dtx * sp[tt][16 + n + 1];
                h[n + 2] = dA[n + 2] * h[n + 2] + dtx * sp[tt][16 + n + 2];
                h[n + 3] = dA[n + 3] * h[n + 3] + dtx * sp[tt][16 + n + 3];
                y0 += h[n + 0] * sp[tt][32 + n + 0];
                y1 += h[n + 1] * sp[tt][32 + n + 1];
                y2 += h[n + 2] * sp[tt][32 + n + 2];
                y3 += h[n + 3] * sp[tt][32 + n + 3];
            }
            float y = (y0 + y1) + (y2 + y3);
            g_y[(size_t)(b * TSEQ + t0 + tt) * DI + d] = (y + xD8[tt]) * gz8[tt];
        }
    }
}

// ---------------- heads with fused final rmsnorm (via rs) ----------------
__global__ void k_heads(const float* __restrict__ fnw, const float* __restrict__ rs,
                        const float* __restrict__ ps_W, const float* __restrict__ ps_b,
                        const float* __restrict__ pa_W, const float* __restrict__ pa_b,
                        float* __restrict__ out)
{
    int idx = blockIdx.x * blockDim.x + threadIdx.x;
    if (idx >= 6144 + 3072) return;
    if (idx < 6144) {
        int j = idx % 6; int l = (idx / 6) % LQ; int b = idx / (6 * LQ);
        int m = b * TSEQ + l * 3 + 2;
        float acc = 0.f;
        const float* f = g_res + (size_t)m * DM;
        #pragma unroll 8
        for (int e = 0; e < DM; e++) acc += f[e] * fnw[e] * ps_W[e * 6 + j];
        out[idx] = acc * rs[m] + ps_b[j];
    } else {
        int k = idx - 6144;
        int j = k % 3; int l = (k / 3) % LQ; int b = k / (3 * LQ);
        int m = b * TSEQ + l * 3 + 1;
        float acc = 0.f;
        const float* f = g_res + (size_t)m * DM;
        #pragma unroll 8
        for (int e = 0; e < DM; e++) acc += f[e] * fnw[e] * pa_W[e * 3 + j];
        out[idx] = tanhf(acc * rs[m] + pa_b[j]);
    }
}

// ---------------- launch ----------------
extern "C" void kernel_launch(void* const* d_in, const int* in_sizes, int n_in,
                              void* d_out, int out_size)
{
    const float* states    = (const float*)d_in[0];
    const float* actions   = (const float*)d_in[1];
    const float* goal      = (const float*)d_in[2];
    const int*   timesteps = (const int*)  d_in[3];
    const float* te_W      = (const float*)d_in[4];
    const float* se_W      = (const float*)d_in[5];
    const float* se_b      = (const float*)d_in[6];
    const float* ge_W      = (const float*)d_in[7];
    const float* ge_b      = (const float*)d_in[8];
    const float* ae_W      = (const float*)d_in[9];
    const float* ae_b      = (const float*)d_in[10];
    const float* bb_in_W   = (const float*)d_in[11];
    const float* bb_in_b   = (const float*)d_in[12];
    const float* norm_w    = (const float*)d_in[13];
    const float* in_proj_W = (const float*)d_in[14];
    const float* conv_w    = (const float*)d_in[15];
    const float* conv_b    = (const float*)d_in[16];
    const float* xproj_W   = (const float*)d_in[17];
    const float* dt_W      = (const float*)d_in[18];
    const float* dt_b      = (const float*)d_in[19];
    const float* A_log     = (const float*)d_in[20];
    const float* Dp        = (const float*)d_in[21];
    const float* out_W     = (const float*)d_in[22];
    const float* fnorm_w   = (const float*)d_in[23];
    const float* ps_W      = (const float*)d_in[24];
    const float* ps_b      = (const float*)d_in[25];
    const float* pa_W      = (const float*)d_in[26];
    const float* pa_b      = (const float*)d_in[27];
    float* out = (float*)d_out;

    float *pu, *pres, *prs, *pxz, *pxc, *pproj, *py;
    cudaGetSymbolAddress((void**)&pu,    g_u);
    cudaGetSymbolAddress((void**)&pres,  g_res);
    cudaGetSymbolAddress((void**)&prs,   g_rs);
    cudaGetSymbolAddress((void**)&pxz,   g_xz);
    cudaGetSymbolAddress((void**)&pxc,   g_xc);
    cudaGetSymbolAddress((void**)&pproj, g_proj);
    cudaGetSymbolAddress((void**)&py,    g_y);

    // 1) embeddings -> u
    k_embed<<<MTOK, DM>>>(states, actions, goal, timesteps, te_W,
                          se_W, se_b, ge_W, ge_b, ae_W, ae_b);

    // 2) residual = u @ bb_in_W + bb_in_b   (fp32; feeds residual base)
    k_gemm_f32<<<dim3(DM / 64, MTOK / 128, 1), 256>>>(
        pu, DM, bb_in_W, DM, DM, bb_in_b, pres, DM);

    // 3) mamba layers
    for (int i = 0; i < NL; i++) {
        const float* inW  = in_proj_W + (size_t)i * DM * 2 * DI;
        const float* cw   = conv_w    + (size_t)i * DI * 4;
        const float* cb   = conv_b    + (size_t)i * DI;
        const float* xpW  = xproj_W   + (size_t)i * DI * 48;
        const float* dtW  = dt_W      + (size_t)i * RK * DI;
        const float* dtb  = dt_b      + (size_t)i * DI;
        const float* Al   = A_log     + (size_t)i * DI * DS;
        const float* Dpi  = Dp        + (size_t)i * DI;
        const float* oW   = out_W     + (size_t)i * DI * DM;
        const float* nw   = norm_w    + (size_t)i * DM;

        // rmsnorm row scales
        k_rowscale<<<MTOK / 8, 256>>>(pres, prs);

        // xz = rmsnorm(res) @ in_W  (TF32 tensor cores, norm folded)
        k_tgemm<0, true><<<dim3(2 * DI / 64, MTOK / 128, 1), 256>>>(
            pres, DM, inW, 2 * DI, DM, prs, nw, pxz, 2 * DI);

        // causal depthwise conv + silu -> xc ; zero proj
        k_conv<<<((MTOK / 4) * (DI / 4)) / 256, 256>>>(cw, cb);

        // proj = xc @ xproj_W  (fp32, split-K x4, atomic)
        k_xproj<<<dim3(1, MTOK / 64, 4), 256>>>(pxc, DI, xpW, 48, DI / 4, pproj, 48);

        // selective scan (fused dt-GEMM + softplus + gate) -> y
        k_scan<<<BQ * 8, 64>>>(Al, Dpi, dtW, dtb);

        // residual += y @ out_W  (TF32 tensor cores, split-K x2, atomic)
        k_tgemm<2, false><<<dim3(DM / 64, MTOK / 128, 2), 256>>>(
            py, DI, oW, DM, DI / 2, nullptr, nullptr, pres, DM);
    }

    // 4) final rmsnorm scales + fused heads
    k_rowscale<<<MTOK / 8, 256>>>(pres, prs);
    k_heads<<<(9216 + 255) / 256, 256>>>(fnorm_w, prs, ps_W, ps_b, pa_W, pa_b, out);
}